// round 17
// baseline (speedup 1.0000x reference)
#include <cuda_runtime.h>
#include <cuda_bf16.h>
#include <cuda_fp16.h>

#define BB 64
#define TT 512
#define DD 512
#define HH 512
#define G3 1536

#define MTOT (BB * TT)
#define KW   (DD / 2)
#define XWRD (MTOT * KW)
#define WWRD (G3 * KW)

// ---------------- device scratch (no allocations allowed) ----------------
__device__ float    g_zi[2][TT][BB][G3];
__device__ unsigned g_xhi[XWRD];
__device__ unsigned g_xlo[XWRD];
__device__ unsigned g_whi[2][WWRD];
__device__ unsigned g_h[2][2][BB * 256];
__device__ unsigned g_cnt[2][512];

// =================================================================
// helpers
// =================================================================
__device__ __forceinline__ unsigned pack2h(float a, float b) {
    __half2 t = __floats2half2_rn(a, b);
    return reinterpret_cast<unsigned&>(t);
}
__device__ __forceinline__ void split2h(float a, float b, unsigned& hi, unsigned& lo) {
    __half ha = __float2half_rn(a), hb = __float2half_rn(b);
    __half2 th = __halves2half2(ha, hb);
    hi = reinterpret_cast<unsigned&>(th);
    lo = pack2h(a - __half2float(ha), b - __half2float(hb));
}
__device__ __forceinline__ float lo16h(unsigned u) {
    __half2 t = reinterpret_cast<__half2&>(u);
    return __half2float(t.x);
}
__device__ __forceinline__ float hi16h(unsigned u) {
    __half2 t = reinterpret_cast<__half2&>(u);
    return __half2float(t.y);
}
__device__ __forceinline__ void mma16816h(float* c, const unsigned* a, const unsigned* b) {
    asm volatile(
        "mma.sync.aligned.m16n8k16.row.col.f32.f16.f16.f32 "
        "{%0,%1,%2,%3}, {%4,%5,%6,%7}, {%8,%9}, {%0,%1,%2,%3};"
        : "+f"(c[0]), "+f"(c[1]), "+f"(c[2]), "+f"(c[3])
        : "r"(a[0]), "r"(a[1]), "r"(a[2]), "r"(a[3]), "r"(b[0]), "r"(b[1]));
}
__device__ __forceinline__ void cp_async16(unsigned smem_addr, const void* gptr) {
    asm volatile("cp.async.cg.shared.global [%0], [%1], 16;\n"
                 :: "r"(smem_addr), "l"(gptr));
}
__device__ __forceinline__ void ldsm4(unsigned addr, unsigned* r) {
    asm volatile("ldmatrix.sync.aligned.m8n8.x4.shared.b16 {%0,%1,%2,%3}, [%4];"
        : "=r"(r[0]), "=r"(r[1]), "=r"(r[2]), "=r"(r[3]) : "r"(addr));
}

// =================================================================
// Kernel 0: split x into fp16 hi/lo; W_ih into fp16 (clock canary)
// =================================================================
__global__ void convert_kernel(const float* __restrict__ x,
                               const float* __restrict__ w_fw,
                               const float* __restrict__ w_bw)
{
    const unsigned idx = blockIdx.x * 256 + threadIdx.x;
    if (idx < XWRD) {
        float2 v = reinterpret_cast<const float2*>(x)[idx];
        split2h(v.x, v.y, g_xhi[idx], g_xlo[idx]);
    } else {
        unsigned w = idx - XWRD;
        if (w < 2u * WWRD) {
            int d = w >= WWRD;
            unsigned o = d ? w - WWRD : w;
            const float* src = d ? w_bw : w_fw;
            float2 v = reinterpret_cast<const float2*>(src)[o];
            g_whi[d][o] = pack2h(v.x, v.y);
        }
    }
}

// =================================================================
// Kernel 1: zi = x @ W_ih^T + b_ih.  NOW 4-stage cp.async
// (3-chunk lookahead), occ 2, R5-proven ordering.
// =================================================================
#define GS_ROWW 20
#define A_MAT (128 * GS_ROWW)
#define B_MAT (64 * GS_ROWW)
// bases: XH_s = s*A_MAT; XL_s = (4+s)*A_MAT; WH_s = 8*A_MAT + s*B_MAT
#define GEMM_SMEM_WORDS (8 * A_MAT + 4 * B_MAT)   // 25600 words = 102,400 B
#define GEMM_SMEM_BYTES (GEMM_SMEM_WORDS * 4)

__global__ void __launch_bounds__(256, 2) gemm_zi_kernel(
    const float* __restrict__ b_fw, const float* __restrict__ b_bw)
{
    extern __shared__ unsigned gsm[];
    const int d = blockIdx.z;
    const float* __restrict__ Bi = d ? b_bw : b_fw;
    const unsigned* __restrict__ wh = g_whi[d];
    float* __restrict__ zi = &g_zi[d][0][0][0];

    const int m0 = blockIdx.y * 128;
    const int n0 = blockIdx.x * 64;
    const int tid  = threadIdx.x;
    const int warp = tid >> 5;
    const int lane = tid & 31;
    const int g    = lane >> 2;
    const int tg   = lane & 3;
    const int wm   = warp >> 2;
    const int wn   = warp & 3;

    const unsigned smem_base = (unsigned)__cvta_generic_to_shared(gsm);

    auto load_stage = [&](int kt, int s) {
#pragma unroll
        for (int i = 0; i < 5; i++) {
            int id = i * 256 + tid;
            const unsigned* src;
            unsigned dstw;
            if (id < 512) {
                int r = id >> 2, c = id & 3;
                src = g_xhi + (size_t)(m0 + r) * KW + kt * 16 + c * 4;
                dstw = s * A_MAT + r * GS_ROWW + c * 4;
            } else if (id < 1024) {
                int rem = id - 512;
                int r = rem >> 2, c = rem & 3;
                src = g_xlo + (size_t)(m0 + r) * KW + kt * 16 + c * 4;
                dstw = (4 + s) * A_MAT + r * GS_ROWW + c * 4;
            } else {
                int rem = id - 1024;
                int r = rem >> 2, c = rem & 3;
                src = wh + (size_t)(n0 + r) * KW + kt * 16 + c * 4;
                dstw = 8 * A_MAT + s * B_MAT + r * GS_ROWW + c * 4;
            }
            cp_async16(smem_base + dstw * 4, src);
        }
        asm volatile("cp.async.commit_group;\n");
    };

    float acc[4][2][4];
#pragma unroll
    for (int mi = 0; mi < 4; mi++)
#pragma unroll
        for (int ni = 0; ni < 2; ni++)
#pragma unroll
            for (int i = 0; i < 4; i++) acc[mi][ni][i] = 0.f;

    load_stage(0, 0);
    load_stage(1, 1);
    load_stage(2, 2);

    const int lr = lane & 15;
    const int lh = (lane >> 4) * 4;

    for (int kt = 0; kt < 16; ++kt) {
        if (kt <= 13)      asm volatile("cp.async.wait_group 2;\n");
        else if (kt == 14) asm volatile("cp.async.wait_group 1;\n");
        else               asm volatile("cp.async.wait_group 0;\n");
        __syncthreads();

        if (kt + 3 < 16) load_stage(kt + 3, (kt + 3) & 3);

        const int st = kt & 3;
        const unsigned baseXH = smem_base + (st * A_MAT) * 4;
        const unsigned baseXL = smem_base + ((4 + st) * A_MAT) * 4;
        const unsigned baseWH = smem_base + (8 * A_MAT + st * B_MAT) * 4;

#pragma unroll
        for (int kk = 0; kk < 2; ++kk) {
            const int kw = kk * 8 + lh;
            unsigned bhi[4];
            {
                unsigned off = ((wn * 16 + lr) * GS_ROWW + kw) * 4;
                ldsm4(baseWH + off, bhi);
            }
            unsigned be[2] = {bhi[0], bhi[2]};
            unsigned bo[2] = {bhi[1], bhi[3]};
#pragma unroll
            for (int mi = 0; mi < 4; mi++) {
                unsigned ahi[4], alo[4];
                unsigned off = ((wm * 64 + mi * 16 + lr) * GS_ROWW + kw) * 4;
                ldsm4(baseXH + off, ahi);
                ldsm4(baseXL + off, alo);
                mma16816h(acc[mi][0], ahi, be);
                mma16816h(acc[mi][0], alo, be);
                mma16816h(acc[mi][1], ahi, bo);
                mma16816h(acc[mi][1], alo, bo);
            }
        }
    }

    float bias[2][2];
#pragma unroll
    for (int ni = 0; ni < 2; ni++) {
        const int n = n0 + wn * 16 + ni * 8 + tg * 2;
        bias[ni][0] = Bi[n]; bias[ni][1] = Bi[n + 1];
    }
#pragma unroll
    for (int mi = 0; mi < 4; mi++) {
        const int row0 = m0 + wm * 64 + mi * 16 + g;
        const int row1 = row0 + 8;
        const int t0 = row0 & (TT - 1), b0r = row0 >> 9;
        const int t1 = row1 & (TT - 1), b1r = row1 >> 9;
        float* d0 = zi + (size_t)(t0 * BB + b0r) * G3;
        float* d1 = zi + (size_t)(t1 * BB + b1r) * G3;
#pragma unroll
        for (int ni = 0; ni < 2; ni++) {
            const int n = n0 + wn * 16 + ni * 8 + tg * 2;
            float2 v0, v1;
            v0.x = acc[mi][ni][0] + bias[ni][0];
            v0.y = acc[mi][ni][1] + bias[ni][1];
            v1.x = acc[mi][ni][2] + bias[ni][0];
            v1.y = acc[mi][ni][3] + bias[ni][1];
            *(float2*)(d0 + n) = v0;
            *(float2*)(d1 + n) = v1;
        }
    }
}

// =================================================================
// Kernel 2: persistent recurrence. NOW 64 blocks (2 dirs x 32
// j-slices of 16): h staged once per block -> chip traffic halves.
// Per k16 per warp: 1 A-ldsm4 + 3 B-ldsm4, 6 MMAs (2 per gate).
// =================================================================
#define WS_STRIDE 260
#define SM_W (48 * WS_STRIDE)          // 48 W rows
#define SM_H (64 * WS_STRIDE)
#define X_STRIDE 25
#define SM_X (4 * 32 * X_STRIDE)       // 3200 floats
#define RNN_SMEM_BYTES ((SM_W + SM_H + SM_X) * 4)

__global__ void __launch_bounds__(256, 1) rnn_kernel(
    const float* __restrict__ whh_fw, const float* __restrict__ whh_bw,
    const float* __restrict__ bhh_fw, const float* __restrict__ bhh_bw,
    float* __restrict__ out)
{
    extern __shared__ unsigned su[];
    unsigned* WHi = su;                          // [48][260] fp16x2
    unsigned* Hs  = su + SM_W;                   // [64][260] fp16x2
    float*    X   = (float*)(su + SM_W + SM_H);

    const int bid = blockIdx.x;
    const int d   = bid >> 5;
    const int sub = bid & 31;
    const int j0  = sub * 16;
    const float* __restrict__ W  = d ? whh_bw : whh_fw;
    const float* __restrict__ Bh = d ? bhh_bw : bhh_fw;

    const int tid  = threadIdx.x;
    const int warp = tid >> 5;
    const int lane = tid & 31;
    const int mt   = warp & 3;
    const int kh   = warp >> 2;
    const int g    = lane >> 2;
    const int tg   = lane & 3;

    auto bar = [&](int idx) {
        __syncthreads();
        if (tid == 0) {
            __threadfence();
            atomicAdd(&g_cnt[d][idx], 1u);
            unsigned v;
            do {
                v = *((volatile unsigned*)&g_cnt[d][idx]);
            } while (v != 0u && v < 32u);
            __threadfence();
        }
        __syncthreads();
    };

    // --- load W_hh slice (48 rows: 16 per gate) as fp16 into SMEM ---
    for (int idx = tid; idx < 48 * 256; idx += 256) {
        int r = idx >> 8, kw = idx & 255;
        int grow = ((r >> 4) << 9) + j0 + (r & 15);
        const float* wr = W + (size_t)grow * HH + kw * 2;
        WHi[r * WS_STRIDE + kw] = pack2h(wr[0], wr[1]);
    }

    const int b0i = mt * 16 + g;
    const int b1i = b0i + 8;
    const int jA0 = j0 + tg * 2;           // half 0
    const int jA1 = j0 + 8 + tg * 2;       // half 1
    const float2 bh_r0 = *(const float2*)&Bh[jA0];
    const float2 bh_z0 = *(const float2*)&Bh[512 + jA0];
    const float2 bh_n0 = *(const float2*)&Bh[1024 + jA0];
    const float2 bh_r1 = *(const float2*)&Bh[jA1];
    const float2 bh_z1 = *(const float2*)&Bh[512 + jA1];
    const float2 bh_n1 = *(const float2*)&Bh[1024 + jA1];
    const int ws0 = (j0 >> 1) + tg;
    const int ws1 = (j0 >> 1) + 4 + tg;

    const unsigned sb = (unsigned)__cvta_generic_to_shared(su);
    const unsigned aAddr = sb + ((SM_W) + (mt * 16 + (lane & 15)) * WS_STRIDE
                                 + (lane >> 4) * 4) * 4;
    const unsigned bR = sb + (((0  + (lane & 15)) * WS_STRIDE) + (lane >> 4) * 4) * 4;
    const unsigned bZ = sb + (((16 + (lane & 15)) * WS_STRIDE) + (lane >> 4) * 4) * 4;
    const unsigned bN = sb + (((32 + (lane & 15)) * WS_STRIDE) + (lane >> 4) * 4) * 4;

    // --- zero h ping buffer 0 (this block's 8 words per batch) ---
    for (int i = tid; i < 512; i += 256) {
        int b = i >> 3, w = (j0 >> 1) + (i & 7);
        g_h[0][d][b * 256 + w] = 0u;
    }
    bar(0);

    const size_t HOFF = (size_t)BB * TT * 1024;

    for (int s = 0; s < TT; ++s) {
        const int p = s & 1;
        const int t = d ? (TT - 1 - s) : s;

        float2 ai[2][3][2];    // [half][gate rzn][batch 0/1]
        if (kh == 0) {
            const float* z0p = &g_zi[d][t][b0i][0];
            const float* z1p = &g_zi[d][t][b1i][0];
            ai[0][0][0] = *(const float2*)&z0p[jA0];
            ai[0][1][0] = *(const float2*)&z0p[512 + jA0];
            ai[0][2][0] = *(const float2*)&z0p[1024 + jA0];
            ai[0][0][1] = *(const float2*)&z1p[jA0];
            ai[0][1][1] = *(const float2*)&z1p[512 + jA0];
            ai[0][2][1] = *(const float2*)&z1p[1024 + jA0];
            ai[1][0][0] = *(const float2*)&z0p[jA1];
            ai[1][1][0] = *(const float2*)&z0p[512 + jA1];
            ai[1][2][0] = *(const float2*)&z0p[1024 + jA1];
            ai[1][0][1] = *(const float2*)&z1p[jA1];
            ai[1][1][1] = *(const float2*)&z1p[512 + jA1];
            ai[1][2][1] = *(const float2*)&z1p[1024 + jA1];
        }

        // --- stage full h in 4 chunks (same as R15/16) ---
        {
            const unsigned* __restrict__ sh = g_h[p][d];
#pragma unroll
            for (int q = 0; q < 4; ++q) {
#pragma unroll
                for (int it = 0; it < 4; ++it) {
                    int j  = it * 256 + tid;
                    int b  = j >> 4;
                    int cl = j & 15;
                    int c  = (cl < 8) ? (q * 8 + cl) : (32 + q * 8 + (cl - 8));
                    int idx = b * 64 + c;
                    unsigned dsth = sb + ((SM_W) + b * WS_STRIDE + c * 4) * 4;
                    cp_async16(dsth, sh + idx * 4);
                }
                asm volatile("cp.async.commit_group;\n");
            }
        }

        float ar[2][4], az[2][4], an[2][4];
#pragma unroll
        for (int h = 0; h < 2; h++)
#pragma unroll
            for (int i = 0; i < 4; i++) { ar[h][i] = 0.f; az[h][i] = 0.f; an[h][i] = 0.f; }

        const unsigned kbase = (unsigned)(kh * 128) * 4;
#pragma unroll
        for (int q = 0; q < 4; ++q) {
            if (q == 0)      asm volatile("cp.async.wait_group 3;\n");
            else if (q == 1) asm volatile("cp.async.wait_group 2;\n");
            else if (q == 2) asm volatile("cp.async.wait_group 1;\n");
            else             asm volatile("cp.async.wait_group 0;\n");
            __syncthreads();

#pragma unroll
            for (int ki = 0; ki < 4; ++ki) {
                const unsigned koff = kbase + (q * 4 + ki) * 32;
                unsigned Af[4];
                ldsm4(aAddr + koff, Af);
                unsigned Br[4], Bz[4], Bn[4];
                ldsm4(bR + koff, Br);
                ldsm4(bZ + koff, Bz);
                ldsm4(bN + koff, Bn);
                unsigned re[2] = {Br[0], Br[2]}, ro[2] = {Br[1], Br[3]};
                unsigned ze[2] = {Bz[0], Bz[2]}, zo[2] = {Bz[1], Bz[3]};
                unsigned ne[2] = {Bn[0], Bn[2]}, no[2] = {Bn[1], Bn[3]};
                mma16816h(ar[0], Af, re); mma16816h(ar[1], Af, ro);
                mma16816h(az[0], Af, ze); mma16816h(az[1], Af, zo);
                mma16816h(an[0], Af, ne); mma16816h(an[1], Af, no);
            }
        }

        if (kh == 1) {
            float* xp = &X[(mt * 32 + lane) * X_STRIDE];
#pragma unroll
            for (int h = 0; h < 2; h++)
#pragma unroll
                for (int i = 0; i < 4; i++) {
                    xp[h * 12 + i]     = ar[h][i];
                    xp[h * 12 + 4 + i] = az[h][i];
                    xp[h * 12 + 8 + i] = an[h][i];
                }
        }
        __syncthreads();

        if (kh == 0) {
            const float* xp = &X[(mt * 32 + lane) * X_STRIDE];
#pragma unroll
            for (int h = 0; h < 2; h++)
#pragma unroll
                for (int i = 0; i < 4; i++) {
                    ar[h][i] += xp[h * 12 + i];
                    az[h][i] += xp[h * 12 + 4 + i];
                    an[h][i] += xp[h * 12 + 8 + i];
                }

#pragma unroll
            for (int h = 0; h < 2; h++) {
                const int jA   = h ? jA1 : jA0;
                const int wsel = h ? ws1 : ws0;
                const float2 bhr = h ? bh_r1 : bh_r0;
                const float2 bhz = h ? bh_z1 : bh_z0;
                const float2 bhn = h ? bh_n1 : bh_n0;

                unsigned uh0 = Hs[b0i * WS_STRIDE + wsel];
                unsigned uh1 = Hs[b1i * WS_STRIDE + wsel];
                float hp00 = lo16h(uh0), hp01 = hi16h(uh0);
                float hp10 = lo16h(uh1), hp11 = hi16h(uh1);

                float r00 = 1.f / (1.f + __expf(-(ai[h][0][0].x + ar[h][0] + bhr.x)));
                float z00 = 1.f / (1.f + __expf(-(ai[h][1][0].x + az[h][0] + bhz.x)));
                float n00 = tanhf(ai[h][2][0].x + r00 * (an[h][0] + bhn.x));
                float h00 = (1.f - z00) * n00 + z00 * hp00;

                float r01 = 1.f / (1.f + __expf(-(ai[h][0][0].y + ar[h][1] + bhr.y)));
                float z01 = 1.f / (1.f + __expf(-(ai[h][1][0].y + az[h][1] + bhz.y)));
                float n01 = tanhf(ai[h][2][0].y + r01 * (an[h][1] + bhn.y));
                float h01 = (1.f - z01) * n01 + z01 * hp01;

                float r10 = 1.f / (1.f + __expf(-(ai[h][0][1].x + ar[h][2] + bhr.x)));
                float z10 = 1.f / (1.f + __expf(-(ai[h][1][1].x + az[h][2] + bhz.x)));
                float n10 = tanhf(ai[h][2][1].x + r10 * (an[h][2] + bhn.x));
                float h10 = (1.f - z10) * n10 + z10 * hp10;

                float r11 = 1.f / (1.f + __expf(-(ai[h][0][1].y + ar[h][3] + bhr.y)));
                float z11 = 1.f / (1.f + __expf(-(ai[h][1][1].y + az[h][3] + bhz.y)));
                float n11 = tanhf(ai[h][2][1].y + r11 * (an[h][3] + bhn.y));
                float h11 = (1.f - z11) * n11 + z11 * hp11;

                g_h[p ^ 1][d][b0i * 256 + wsel] = pack2h(h00, h01);
                g_h[p ^ 1][d][b1i * 256 + wsel] = pack2h(h10, h11);

                float2 o0; o0.x = h00; o0.y = h01;
                float2 o1; o1.x = h10; o1.y = h11;
                *(float2*)&out[(size_t)(b0i * TT + t) * 1024 + d * 512 + jA] = o0;
                *(float2*)&out[(size_t)(b1i * TT + t) * 1024 + d * 512 + jA] = o1;
                if (s == TT - 1) {
                    *(float2*)&out[HOFF + (size_t)d * BB * HH + b0i * HH + jA] = o0;
                    *(float2*)&out[HOFF + (size_t)d * BB * HH + b1i * HH + jA] = o1;
                }
            }
        }
        if (s < TT - 1) bar(s + 1);
    }

    // reset counters for next graph replay (safe: spin treats 0 as done)
    if (tid == 0) {
        for (int i = sub; i < 512; i += 32) g_cnt[d][i] = 0u;
    }
}

// =================================================================
extern "C" void kernel_launch(void* const* d_in, const int* in_sizes, int n_in,
                              void* d_out, int out_size)
{
    const float* x       = (const float*)d_in[0];
    const float* w_ih_fw = (const float*)d_in[1];
    const float* w_hh_fw = (const float*)d_in[2];
    const float* b_ih_fw = (const float*)d_in[3];
    const float* b_hh_fw = (const float*)d_in[4];
    const float* w_ih_bw = (const float*)d_in[5];
    const float* w_hh_bw = (const float*)d_in[6];
    const float* b_ih_bw = (const float*)d_in[7];
    const float* b_hh_bw = (const float*)d_in[8];
    float* out = (float*)d_out;

    cudaFuncSetAttribute(gemm_zi_kernel, cudaFuncAttributeMaxDynamicSharedMemorySize,
                         GEMM_SMEM_BYTES);
    cudaFuncSetAttribute(rnn_kernel, cudaFuncAttributeMaxDynamicSharedMemorySize,
                         RNN_SMEM_BYTES);

    const unsigned total_words = XWRD + 2 * WWRD;
    convert_kernel<<<(total_words + 255) / 256, 256>>>(x, w_ih_fw, w_ih_bw);

    dim3 ggrid(G3 / 64, MTOT / 128, 2);
    gemm_zi_kernel<<<ggrid, 256, GEMM_SMEM_BYTES>>>(b_ih_fw, b_ih_bw);

    rnn_kernel<<<64, 256, RNN_SMEM_BYTES>>>(w_hh_fw, w_hh_bw, b_hh_fw, b_hh_bw, out);
}